// round 16
// baseline (speedup 1.0000x reference)
#include <cuda_runtime.h>
#include <cuda_fp16.h>
#include <cstdint>

#define DM   1024
#define NE   8
#define FF   2048
#define MAXT 4096
#define TKC  64
#define NSTG 3
#define STGW (256 * 32)      // words per stage: 256 rows x 32 words (64 fp16)
#define STGB (STGW * 4)      // 32768 bytes

// -------- persistent device scratch (no dynamic alloc allowed) -------------
__device__ int    g_cnt[NE];
__device__ int    g_tok[NE * MAXT];
__device__ float  g_wt [NE * MAXT];
__device__ __half g_xh  [(size_t)MAXT * DM];
__device__ __half g_w1h [(size_t)NE * 2 * FF * DM];
__device__ __half g_w2h [(size_t)NE * DM * FF];
__device__ __half g_acth[(size_t)NE * MAXT * FF];

// ---------------------------------------------------------------------------
__device__ __forceinline__ uint32_t smem_u32(const void* p) {
    uint32_t a;
    asm("{ .reg .u64 t; cvta.to.shared.u64 t, %1; cvt.u32.u64 %0, t; }" : "=r"(a) : "l"(p));
    return a;
}
__device__ __forceinline__ void cpa16(uint32_t dst, const void* src, int sz) {
    asm volatile("cp.async.cg.shared.global [%0], [%1], 16, %2;"
                 :: "r"(dst), "l"(src), "r"(sz) : "memory");
}
#define CP_COMMIT() asm volatile("cp.async.commit_group;" ::: "memory")
#define CP_WAIT1()  asm volatile("cp.async.wait_group 1;" ::: "memory")
#define CP_WAIT0()  asm volatile("cp.async.wait_group 0;" ::: "memory")

// 32-word (128B) rows; 16B-quad q ^= (row & 7) -> conflict-free frags
__device__ __forceinline__ uint32_t swo(int row, int q) {
    return (uint32_t)(row * 32 + ((q ^ (row & 7)) << 2));
}

__device__ __forceinline__ void mma16(float c[4], const uint32_t a[4], const uint32_t b[2]) {
    asm volatile(
        "mma.sync.aligned.m16n8k16.row.col.f32.f16.f16.f32 "
        "{%0,%1,%2,%3}, {%4,%5,%6,%7}, {%8,%9}, {%0,%1,%2,%3};"
        : "+f"(c[0]), "+f"(c[1]), "+f"(c[2]), "+f"(c[3])
        : "r"(a[0]), "r"(a[1]), "r"(a[2]), "r"(a[3]), "r"(b[0]), "r"(b[1]));
}

// ---------------------------------------------------------------------------
__global__ void init_k() { if (threadIdx.x < NE) g_cnt[threadIdx.x] = 0; }

__global__ void cvt16_k(const float* __restrict__ src, __half* __restrict__ dst, int n4) {
    int i = blockIdx.x * blockDim.x + threadIdx.x;
    int st = gridDim.x * blockDim.x;
    for (; i < n4; i += st) {
        float4 v = ((const float4*)src)[i];
        __half2* d = (__half2*)dst + 2 * i;
        d[0] = __floats2half2_rn(v.x, v.y);
        d[1] = __floats2half2_rn(v.z, v.w);
    }
}

__global__ void router_k(const float* __restrict__ x,
                         const float* __restrict__ Wr,
                         const float* __restrict__ temp) {
    __shared__ float xs[DM];
    __shared__ float lg[NE];
    int t = blockIdx.x;
    const float* xr = x + (size_t)t * DM;
    for (int i = threadIdx.x; i < DM; i += blockDim.x) xs[i] = xr[i];
    __syncthreads();
    __half2* xh2 = (__half2*)(g_xh + (size_t)t * DM);
    for (int i = threadIdx.x; i < DM / 2; i += blockDim.x)
        xh2[i] = __floats2half2_rn(xs[2 * i], xs[2 * i + 1]);
    int w = threadIdx.x >> 5, lane = threadIdx.x & 31;
    if (w < NE) {
        const float* wr = Wr + (size_t)w * DM;
        float s = 0.f;
        for (int i = lane; i < DM; i += 32) s += xs[i] * wr[i];
        #pragma unroll
        for (int o = 16; o; o >>= 1) s += __shfl_xor_sync(0xffffffffu, s, o);
        if (lane == 0) lg[w] = s;
    }
    __syncthreads();
    if (threadIdx.x == 0) {
        float it = 1.f / temp[0];
        float l[NE];
        #pragma unroll
        for (int e = 0; e < NE; e++) l[e] = lg[e] * it;
        int i0 = 0;
        #pragma unroll
        for (int e = 1; e < NE; e++) if (l[e] > l[i0]) i0 = e;
        int i1 = (i0 == 0) ? 1 : 0;
        #pragma unroll
        for (int e = 0; e < NE; e++) if (e != i0 && l[e] > l[i1]) i1 = e;
        float m  = l[i0];
        float e0 = __expf(l[i0] - m), e1 = __expf(l[i1] - m);
        float inv = 1.f / (e0 + e1);
        int s0 = atomicAdd(&g_cnt[i0], 1);
        g_tok[i0 * MAXT + s0] = t;  g_wt[i0 * MAXT + s0] = e0 * inv;
        int s1 = atomicAdd(&g_cnt[i1], 1);
        g_tok[i1 * MAXT + s1] = t;  g_wt[i1 * MAXT + s1] = e1 * inv;
    }
}

// ---------------------------------------------------------------------------
// GEMM1: CTA 128(M) x 64(N) over BOTH W1 halves (B tile = 128 rows), fp16 smem.
__global__ __launch_bounds__(128, 2) void gemm1_k(const float* __restrict__ b1, int e) {
    int cnt = g_cnt[e];
    int m0  = blockIdx.y * 128;
    if (m0 >= cnt) return;
    int n0  = blockIdx.x * 64;

    extern __shared__ uint32_t dynw[];
    uint32_t sb = smem_u32(dynw);
    __shared__ int toks[128];

    int tid = threadIdx.x, wid = tid >> 5, lane = tid & 31;
    int g = lane >> 2, tig = lane & 3;
    int wm = (wid & 1) * 64, wn = (wid >> 1) * 32;

    if (tid < 128) { int m = m0 + tid; toks[tid] = (m < cnt) ? g_tok[e * MAXT + m] : -1; }
    __syncthreads();

    const __half* W1e = g_w1h + (size_t)e * (2 * FF) * DM;

    float acc[2][4][4][4];
    #pragma unroll
    for (int h = 0; h < 2; h++)
        #pragma unroll
        for (int mt = 0; mt < 4; mt++)
            #pragma unroll
            for (int nt = 0; nt < 4; nt++)
                #pragma unroll
                for (int j = 0; j < 4; j++) acc[h][mt][nt][j] = 0.f;

    const int NC = DM / TKC;    // 16

    #define ISSUE1_PART(c, s, p) do {                                           \
        int k0_ = (c) * TKC;                                                    \
        uint32_t st_ = sb + (uint32_t)(s) * STGB;                               \
        _Pragma("unroll")                                                       \
        for (int i_ = (p) * 4; i_ < (p) * 4 + 4; i_++) {                        \
            int idx_ = tid + i_ * 128, row_ = idx_ >> 3, q_ = idx_ & 7;         \
            uint32_t dst_ = st_ + swo(row_, q_) * 4;                            \
            if (row_ < 128) {                                                   \
                int tok_ = toks[row_];                                          \
                const __half* src_ = g_xh + (size_t)(tok_ < 0 ? 0 : tok_) * DM  \
                                     + k0_ + q_ * 8;                            \
                cpa16(dst_, src_, tok_ >= 0 ? 16 : 0);                          \
            } else {                                                            \
                int j_ = row_ - 128, h_ = j_ >> 6, jr_ = j_ & 63;               \
                const __half* src_ = W1e + (size_t)(h_ * FF + n0 + jr_) * DM    \
                                     + k0_ + q_ * 8;                            \
                cpa16(dst_, src_, 16);                                          \
            }                                                                   \
        }                                                                       \
    } while (0)

    #define ISSUE1(c, s) do {                                                   \
        ISSUE1_PART(c, s, 0); ISSUE1_PART(c, s, 1);                             \
        ISSUE1_PART(c, s, 2); ISSUE1_PART(c, s, 3);                             \
        CP_COMMIT();                                                            \
    } while (0)

    #define LDFRAG1(buf, ST, kk) do {                                           \
        int q0_ = (kk) >> 3;                                                    \
        _Pragma("unroll")                                                       \
        for (int mt = 0; mt < 4; mt++) {                                        \
            int rb = wm + mt * 16;                                              \
            af[buf][mt][0] = ST[swo(rb + g,     q0_)     + tig];                \
            af[buf][mt][1] = ST[swo(rb + g + 8, q0_)     + tig];                \
            af[buf][mt][2] = ST[swo(rb + g,     q0_ + 1) + tig];                \
            af[buf][mt][3] = ST[swo(rb + g + 8, q0_ + 1) + tig];                \
        }                                                                       \
        _Pragma("unroll")                                                       \
        for (int h = 0; h < 2; h++)                                             \
            _Pragma("unroll")                                                   \
            for (int nt = 0; nt < 4; nt++) {                                    \
                int rb = 128 + h * 64 + wn + nt * 8 + g;                        \
                bf[buf][h][nt][0] = ST[swo(rb, q0_)     + tig];                 \
                bf[buf][h][nt][1] = ST[swo(rb, q0_ + 1) + tig];                 \
            }                                                                   \
    } while (0)

    ISSUE1(0, 0); ISSUE1(1, 1);

    uint32_t af[2][4][4];
    uint32_t bf[2][2][4][2];

    for (int c = 0; c < NC; ++c) {
        if (c + 1 < NC) CP_WAIT1(); else CP_WAIT0();
        __syncthreads();
        const uint32_t* ST = dynw + (c % NSTG) * STGW;
        int pre = (c + 2 < NC);
        int s2  = (c + 2) % NSTG;
        LDFRAG1(0, ST, 0);
        #pragma unroll
        for (int kk = 0; kk < TKC; kk += 16) {
            int cur = (kk >> 4) & 1;
            if (pre) ISSUE1_PART(c + 2, s2, kk >> 4);
            if (kk + 16 < TKC) LDFRAG1(cur ^ 1, ST, kk + 16);
            #pragma unroll
            for (int h = 0; h < 2; h++)
                #pragma unroll
                for (int mt = 0; mt < 4; mt++)
                    #pragma unroll
                    for (int nt = 0; nt < 4; nt++)
                        mma16(acc[h][mt][nt], af[cur][mt], bf[cur][h][nt]);
        }
        if (pre) CP_COMMIT();
    }

    const float* b1e  = b1 + (size_t)e * 2 * FF;
    __half*      acte = g_acth + (size_t)e * MAXT * FF;
    #pragma unroll
    for (int mt = 0; mt < 4; mt++)
        #pragma unroll
        for (int rr = 0; rr < 2; rr++) {
            int mg = m0 + wm + mt * 16 + g + rr * 8;
            if (mg >= cnt) continue;
            __half* orow = acte + (size_t)mg * FF;
            #pragma unroll
            for (int nt = 0; nt < 4; nt++) {
                int col = n0 + wn + nt * 8 + tig * 2;
                float h1a = acc[0][mt][nt][rr * 2 + 0] + b1e[col];
                float h1b = acc[0][mt][nt][rr * 2 + 1] + b1e[col + 1];
                float h2a = acc[1][mt][nt][rr * 2 + 0] + b1e[FF + col];
                float h2b = acc[1][mt][nt][rr * 2 + 1] + b1e[FF + col + 1];
                float oa = h1a * h2a / (1.f + __expf(-h2a));
                float ob = h1b * h2b / (1.f + __expf(-h2b));
                *(__half2*)(orow + col) = __floats2half2_rn(oa, ob);
            }
        }
    #undef ISSUE1
    #undef ISSUE1_PART
    #undef LDFRAG1
}

// ---------------------------------------------------------------------------
// GEMM2: CTA 128(M) x 128(N); 4 warps 2x2; warp tile 64x64; atomic scatter.
__global__ __launch_bounds__(128, 2) void gemm2_k(const float* __restrict__ b2,
                                                  float* __restrict__ out, int e) {
    int cnt = g_cnt[e];
    int m0  = blockIdx.y * 128;
    if (m0 >= cnt) return;
    int n0  = blockIdx.x * 128;

    extern __shared__ uint32_t dynw[];
    uint32_t sb = smem_u32(dynw);
    __shared__ int   toks[128];
    __shared__ float wts[128];

    int tid = threadIdx.x, wid = tid >> 5, lane = tid & 31;
    int g = lane >> 2, tig = lane & 3;
    int wm = (wid & 1) * 64, wn = (wid >> 1) * 64;

    if (tid < 128) {
        int m = m0 + tid;
        toks[tid] = (m < cnt) ? g_tok[e * MAXT + m] : -1;
        wts[tid]  = (m < cnt) ? g_wt[e * MAXT + m] : 0.f;
    }
    __syncthreads();

    const __half* W2e  = g_w2h + (size_t)e * DM * FF;
    const __half* acte = g_acth + (size_t)e * MAXT * FF;

    float acc[4][8][4];
    #pragma unroll
    for (int mt = 0; mt < 4; mt++)
        #pragma unroll
        for (int nt = 0; nt < 8; nt++)
            #pragma unroll
            for (int j = 0; j < 4; j++) acc[mt][nt][j] = 0.f;

    const int NC = FF / TKC;    // 32

    #define ISSUE2_PART(c, s, p) do {                                           \
        int k0_ = (c) * TKC;                                                    \
        uint32_t st_ = sb + (uint32_t)(s) * STGB;                               \
        _Pragma("unroll")                                                       \
        for (int i_ = (p) * 4; i_ < (p) * 4 + 4; i_++) {                        \
            int idx_ = tid + i_ * 128, row_ = idx_ >> 3, q_ = idx_ & 7;         \
            uint32_t dst_ = st_ + swo(row_, q_) * 4;                            \
            if (row_ < 128) {                                                   \
                int ok_ = (m0 + row_ < cnt);                                    \
                const __half* src_ = acte + (size_t)(m0 + (ok_ ? row_ : 0)) * FF\
                                     + k0_ + q_ * 8;                            \
                cpa16(dst_, src_, ok_ ? 16 : 0);                                \
            } else {                                                            \
                int j_ = row_ - 128;                                            \
                const __half* src_ = W2e + (size_t)(n0 + j_) * FF + k0_ + q_ * 8;\
                cpa16(dst_, src_, 16);                                          \
            }                                                                   \
        }                                                                       \
    } while (0)

    #define ISSUE2(c, s) do {                                                   \
        ISSUE2_PART(c, s, 0); ISSUE2_PART(c, s, 1);                             \
        ISSUE2_PART(c, s, 2); ISSUE2_PART(c, s, 3);                             \
        CP_COMMIT();                                                            \
    } while (0)

    #define LDFRAG2(buf, ST, kk) do {                                           \
        int q0_ = (kk) >> 3;                                                    \
        _Pragma("unroll")                                                       \
        for (int mt = 0; mt < 4; mt++) {                                        \
            int rb = wm + mt * 16;                                              \
            af[buf][mt][0] = ST[swo(rb + g,     q0_)     + tig];                \
            af[buf][mt][1] = ST[swo(rb + g + 8, q0_)     + tig];                \
            af[buf][mt][2] = ST[swo(rb + g,     q0_ + 1) + tig];                \
            af[buf][mt][3] = ST[swo(rb + g + 8, q0_ + 1) + tig];                \
        }                                                                       \
        _Pragma("unroll")                                                       \
        for (int nt = 0; nt < 8; nt++) {                                        \
            int rb = 128 + wn + nt * 8 + g;                                     \
            bf[buf][nt][0] = ST[swo(rb, q0_)     + tig];                        \
            bf[buf][nt][1] = ST[swo(rb, q0_ + 1) + tig];                        \
        }                                                                       \
    } while (0)

    ISSUE2(0, 0); ISSUE2(1, 1);

    uint32_t af[2][4][4];
    uint32_t bf[2][8][2];

    for (int c = 0; c < NC; ++c) {
        if (c + 1 < NC) CP_WAIT1(); else CP_WAIT0();
        __syncthreads();
        const uint32_t* ST = dynw + (c % NSTG) * STGW;
        int pre = (c + 2 < NC);
        int s2  = (c + 2) % NSTG;
        LDFRAG2(0, ST, 0);
        #pragma unroll
        for (int kk = 0; kk < TKC; kk += 16) {
            int cur = (kk >> 4) & 1;
            if (pre) ISSUE2_PART(c + 2, s2, kk >> 4);
            if (kk + 16 < TKC) LDFRAG2(cur ^ 1, ST, kk + 16);
            #pragma unroll
            for (int mt = 0; mt < 4; mt++)
                #pragma unroll
                for (int nt = 0; nt < 8; nt++)
                    mma16(acc[mt][nt], af[cur][mt], bf[cur][nt]);
        }
        if (pre) CP_COMMIT();
    }

    const float* b2e = b2 + (size_t)e * DM;
    #pragma unroll
    for (int mt = 0; mt < 4; mt++)
        #pragma unroll
        for (int rr = 0; rr < 2; rr++) {
            int lm = wm + mt * 16 + g + rr * 8;
            int mg = m0 + lm;
            if (mg >= cnt) continue;
            int   tok = toks[lm];
            float w   = wts[lm];
            float* dst = out + (size_t)tok * DM;
            #pragma unroll
            for (int nt = 0; nt < 8; nt++) {
                int col = n0 + wn + nt * 8 + tig * 2;
                atomicAdd(dst + col,     w * (acc[mt][nt][rr * 2 + 0] + b2e[col]));
                atomicAdd(dst + col + 1, w * (acc[mt][nt][rr * 2 + 1] + b2e[col + 1]));
            }
        }
    #undef ISSUE2
    #undef ISSUE2_PART
    #undef LDFRAG2
}

// ---------------------------------------------------------------------------
extern "C" void kernel_launch(void* const* d_in, const int* in_sizes, int n_in,
                              void* d_out, int out_size) {
    const float* x    = (const float*)d_in[0];
    const float* Wr   = (const float*)d_in[1];
    const float* temp = (const float*)d_in[2];
    const float* W1   = (const float*)d_in[3];
    const float* b1   = (const float*)d_in[4];
    const float* W2   = (const float*)d_in[5];
    const float* b2   = (const float*)d_in[6];
    float* out = (float*)d_out;

    int T  = in_sizes[0] / DM;
    int MB = (T + 127) / 128;

    static __half *p_w1h = nullptr, *p_w2h = nullptr;
    static cudaStream_t s1, s2;
    static cudaEvent_t ev_fork, ev_router, ev_d1, ev_d2;
    static bool inited = false;
    if (!inited) {
        cudaGetSymbolAddress((void**)&p_w1h, g_w1h);
        cudaGetSymbolAddress((void**)&p_w2h, g_w2h);
        cudaStreamCreateWithFlags(&s1, cudaStreamNonBlocking);
        cudaStreamCreateWithFlags(&s2, cudaStreamNonBlocking);
        cudaEventCreateWithFlags(&ev_fork, cudaEventDisableTiming);
        cudaEventCreateWithFlags(&ev_router, cudaEventDisableTiming);
        cudaEventCreateWithFlags(&ev_d1, cudaEventDisableTiming);
        cudaEventCreateWithFlags(&ev_d2, cudaEventDisableTiming);
        const int DSM = NSTG * STGB;   // 98304
        cudaFuncSetAttribute(gemm1_k, cudaFuncAttributeMaxDynamicSharedMemorySize, DSM);
        cudaFuncSetAttribute(gemm2_k, cudaFuncAttributeMaxDynamicSharedMemorySize, DSM);
        inited = true;
    }
    const int DSM  = NSTG * STGB;
    const int W1E4 = 2 * FF * DM / 4;   // float4 count per expert W1 slice
    const int W2E4 = DM * FF / 4;

    // stream 0: memset -> init -> router
    cudaMemsetAsync(d_out, 0, (size_t)out_size * sizeof(float), 0);
    init_k<<<1, 32, 0, 0>>>();
    cudaEventRecord(ev_fork, 0);
    router_k<<<T, 256, 0, 0>>>(x, Wr, temp);
    cudaEventRecord(ev_router, 0);

    dim3 g1(FF / 64, MB);
    dim3 g2(DM / 128, MB);

    cudaStreamWaitEvent(s1, ev_fork, 0);
    cudaStreamWaitEvent(s2, ev_fork, 0);

    // per-stream: convert own experts' weights (overlaps router), then chains
    for (int e = 0; e < 4; e++) {
        cvt16_k<<<148, 256, 0, s1>>>(W1 + (size_t)e * 2 * FF * DM,
                                     p_w1h + (size_t)e * 2 * FF * DM, W1E4);
        cvt16_k<<<148, 256, 0, s1>>>(W2 + (size_t)e * DM * FF,
                                     p_w2h + (size_t)e * DM * FF, W2E4);
    }
    for (int e = 4; e < NE; e++) {
        cvt16_k<<<148, 256, 0, s2>>>(W1 + (size_t)e * 2 * FF * DM,
                                     p_w1h + (size_t)e * 2 * FF * DM, W1E4);
        cvt16_k<<<148, 256, 0, s2>>>(W2 + (size_t)e * DM * FF,
                                     p_w2h + (size_t)e * DM * FF, W2E4);
    }

    cudaStreamWaitEvent(s1, ev_router, 0);
    cudaStreamWaitEvent(s2, ev_router, 0);

    for (int e = 0; e < 4; e++) {
        gemm1_k<<<g1, 128, DSM, s1>>>(b1, e);
        gemm2_k<<<g2, 128, DSM, s1>>>(b2, out, e);
    }
    for (int e = 4; e < NE; e++) {
        gemm1_k<<<g1, 128, DSM, s2>>>(b1, e);
        gemm2_k<<<g2, 128, DSM, s2>>>(b2, out, e);
    }

    cudaEventRecord(ev_d1, s1);
    cudaEventRecord(ev_d2, s2);
    cudaStreamWaitEvent(0, ev_d1, 0);
    cudaStreamWaitEvent(0, ev_d2, 0);
}

// round 17
// speedup vs baseline: 1.2797x; 1.2797x over previous
#include <cuda_runtime.h>
#include <cuda_fp16.h>
#include <cstdint>

#define DM   1024
#define NE   8
#define FF   2048
#define MAXT 4096
#define TKC  64
#define NSTG 3
#define STGW (256 * 32)      // words per stage: 256 rows x 32 words (64 fp16)
#define STGB (STGW * 4)      // 32768 bytes

// -------- persistent device scratch (no dynamic alloc allowed) -------------
__device__ int    g_cnt[NE];
__device__ int    g_tok[NE * MAXT];
__device__ float  g_wt [NE * MAXT];
__device__ __half g_xh  [(size_t)MAXT * DM];
__device__ __half g_w1h [(size_t)NE * 2 * FF * DM];
__device__ __half g_w2h [(size_t)NE * DM * FF];
__device__ __half g_acth[(size_t)NE * MAXT * FF];

// ---------------------------------------------------------------------------
__device__ __forceinline__ uint32_t smem_u32(const void* p) {
    uint32_t a;
    asm("{ .reg .u64 t; cvta.to.shared.u64 t, %1; cvt.u32.u64 %0, t; }" : "=r"(a) : "l"(p));
    return a;
}
__device__ __forceinline__ void cpa16(uint32_t dst, const void* src, int sz) {
    asm volatile("cp.async.cg.shared.global [%0], [%1], 16, %2;"
                 :: "r"(dst), "l"(src), "r"(sz) : "memory");
}
#define CP_COMMIT() asm volatile("cp.async.commit_group;" ::: "memory")
#define CP_WAIT1()  asm volatile("cp.async.wait_group 1;" ::: "memory")
#define CP_WAIT0()  asm volatile("cp.async.wait_group 0;" ::: "memory")

// 32-word (128B) rows; 16B-quad q ^= (row & 7) -> conflict-free frags/LDSM
__device__ __forceinline__ uint32_t swo(int row, int q) {
    return (uint32_t)(row * 32 + ((q ^ (row & 7)) << 2));
}

__device__ __forceinline__ void ldsm4(uint32_t* r, uint32_t addr) {
    asm volatile("ldmatrix.sync.aligned.m8n8.x4.shared.b16 {%0,%1,%2,%3}, [%4];"
                 : "=r"(r[0]), "=r"(r[1]), "=r"(r[2]), "=r"(r[3]) : "r"(addr));
}

__device__ __forceinline__ void mma16(float c[4], const uint32_t a[4], const uint32_t b[2]) {
    asm volatile(
        "mma.sync.aligned.m16n8k16.row.col.f32.f16.f16.f32 "
        "{%0,%1,%2,%3}, {%4,%5,%6,%7}, {%8,%9}, {%0,%1,%2,%3};"
        : "+f"(c[0]), "+f"(c[1]), "+f"(c[2]), "+f"(c[3])
        : "r"(a[0]), "r"(a[1]), "r"(a[2]), "r"(a[3]), "r"(b[0]), "r"(b[1]));
}

// ---------------------------------------------------------------------------
__global__ void init_k() { if (threadIdx.x < NE) g_cnt[threadIdx.x] = 0; }

__global__ void cvt16_k(const float* __restrict__ src, __half* __restrict__ dst, int n4) {
    int i = blockIdx.x * blockDim.x + threadIdx.x;
    int st = gridDim.x * blockDim.x;
    for (; i < n4; i += st) {
        float4 v = ((const float4*)src)[i];
        __half2* d = (__half2*)dst + 2 * i;
        d[0] = __floats2half2_rn(v.x, v.y);
        d[1] = __floats2half2_rn(v.z, v.w);
    }
}

__global__ void router_k(const float* __restrict__ x,
                         const float* __restrict__ Wr,
                         const float* __restrict__ temp) {
    __shared__ float xs[DM];
    __shared__ float lg[NE];
    int t = blockIdx.x;
    const float* xr = x + (size_t)t * DM;
    for (int i = threadIdx.x; i < DM; i += blockDim.x) xs[i] = xr[i];
    __syncthreads();
    __half2* xh2 = (__half2*)(g_xh + (size_t)t * DM);
    for (int i = threadIdx.x; i < DM / 2; i += blockDim.x)
        xh2[i] = __floats2half2_rn(xs[2 * i], xs[2 * i + 1]);
    int w = threadIdx.x >> 5, lane = threadIdx.x & 31;
    if (w < NE) {
        const float* wr = Wr + (size_t)w * DM;
        float s = 0.f;
        for (int i = lane; i < DM; i += 32) s += xs[i] * wr[i];
        #pragma unroll
        for (int o = 16; o; o >>= 1) s += __shfl_xor_sync(0xffffffffu, s, o);
        if (lane == 0) lg[w] = s;
    }
    __syncthreads();
    if (threadIdx.x == 0) {
        float it = 1.f / temp[0];
        float l[NE];
        #pragma unroll
        for (int e = 0; e < NE; e++) l[e] = lg[e] * it;
        int i0 = 0;
        #pragma unroll
        for (int e = 1; e < NE; e++) if (l[e] > l[i0]) i0 = e;
        int i1 = (i0 == 0) ? 1 : 0;
        #pragma unroll
        for (int e = 0; e < NE; e++) if (e != i0 && l[e] > l[i1]) i1 = e;
        float m  = l[i0];
        float e0 = __expf(l[i0] - m), e1 = __expf(l[i1] - m);
        float inv = 1.f / (e0 + e1);
        int s0 = atomicAdd(&g_cnt[i0], 1);
        g_tok[i0 * MAXT + s0] = t;  g_wt[i0 * MAXT + s0] = e0 * inv;
        int s1 = atomicAdd(&g_cnt[i1], 1);
        g_tok[i1 * MAXT + s1] = t;  g_wt[i1 * MAXT + s1] = e1 * inv;
    }
}

// ---------------------------------------------------------------------------
// GEMM1: CTA 128(M) x 64(N) over BOTH W1 halves (B tile = 128 rows), fp16 smem.
__global__ __launch_bounds__(128, 2) void gemm1_k(const float* __restrict__ b1) {
    int e   = blockIdx.z;
    int cnt = g_cnt[e];
    int m0  = blockIdx.y * 128;
    if (m0 >= cnt) return;
    int n0  = blockIdx.x * 64;

    extern __shared__ uint32_t dynw[];
    uint32_t sb = smem_u32(dynw);
    __shared__ int toks[128];

    int tid = threadIdx.x, wid = tid >> 5, lane = tid & 31;
    int g = lane >> 2, tig = lane & 3;
    int wm = (wid & 1) * 64, wn = (wid >> 1) * 32;

    // ldmatrix lane address components
    int sel = lane >> 3, r7 = lane & 7;
    int      arow_off = r7 + ((sel & 1) << 3);
    uint32_t axoff    = (uint32_t)((((sel >> 1) ^ r7) << 4));
    int      brow_off = r7 + ((sel >> 1) << 3);
    uint32_t bxoff    = (uint32_t)((((sel & 1) ^ r7) << 4));

    if (tid < 128) { int m = m0 + tid; toks[tid] = (m < cnt) ? g_tok[e * MAXT + m] : -1; }
    __syncthreads();

    const __half* W1e = g_w1h + (size_t)e * (2 * FF) * DM;

    float acc[2][4][4][4];
    #pragma unroll
    for (int h = 0; h < 2; h++)
        #pragma unroll
        for (int mt = 0; mt < 4; mt++)
            #pragma unroll
            for (int nt = 0; nt < 4; nt++)
                #pragma unroll
                for (int j = 0; j < 4; j++) acc[h][mt][nt][j] = 0.f;

    const int NC = DM / TKC;    // 16

    #define ISSUE1_PART(c, s, p) do {                                           \
        int k0_ = (c) * TKC;                                                    \
        uint32_t st_ = sb + (uint32_t)(s) * STGB;                               \
        _Pragma("unroll")                                                       \
        for (int i_ = (p) * 4; i_ < (p) * 4 + 4; i_++) {                        \
            int idx_ = tid + i_ * 128, row_ = idx_ >> 3, q_ = idx_ & 7;         \
            uint32_t dst_ = st_ + swo(row_, q_) * 4;                            \
            if (row_ < 128) {                                                   \
                int tok_ = toks[row_];                                          \
                const __half* src_ = g_xh + (size_t)(tok_ < 0 ? 0 : tok_) * DM  \
                                     + k0_ + q_ * 8;                            \
                cpa16(dst_, src_, tok_ >= 0 ? 16 : 0);                          \
            } else {                                                            \
                int j_ = row_ - 128, h_ = j_ >> 6, jr_ = j_ & 63;               \
                const __half* src_ = W1e + (size_t)(h_ * FF + n0 + jr_) * DM    \
                                     + k0_ + q_ * 8;                            \
                cpa16(dst_, src_, 16);                                          \
            }                                                                   \
        }                                                                       \
    } while (0)

    #define ISSUE1(c, s) do {                                                   \
        ISSUE1_PART(c, s, 0); ISSUE1_PART(c, s, 1);                             \
        ISSUE1_PART(c, s, 2); ISSUE1_PART(c, s, 3);                             \
        CP_COMMIT();                                                            \
    } while (0)

    // ldmatrix fragments for K=16 step at kk
    #define LDFRAG1(buf, stb, kk) do {                                          \
        uint32_t qx_ = ((uint32_t)((kk) >> 3)) << 4;                            \
        _Pragma("unroll")                                                       \
        for (int mt = 0; mt < 4; mt++)                                          \
            ldsm4(af[buf][mt],                                                  \
                  (stb) + (uint32_t)((wm + mt * 16 + arow_off) * 128)           \
                        + (axoff ^ qx_));                                       \
        _Pragma("unroll")                                                       \
        for (int h = 0; h < 2; h++)                                             \
            _Pragma("unroll")                                                   \
            for (int np = 0; np < 2; np++)                                      \
                ldsm4(&bf[buf][h][np * 2][0],                                   \
                      (stb) + (uint32_t)((128 + h * 64 + wn + np * 16           \
                                          + brow_off) * 128)                    \
                            + (bxoff ^ qx_));                                   \
    } while (0)

    ISSUE1(0, 0); ISSUE1(1, 1);

    uint32_t af[2][4][4];
    uint32_t bf[2][2][4][2];

    for (int c = 0; c < NC; ++c) {
        if (c + 1 < NC) CP_WAIT1(); else CP_WAIT0();
        __syncthreads();
        uint32_t stb = sb + (uint32_t)(c % NSTG) * STGB;
        int pre = (c + 2 < NC);
        int s2  = (c + 2) % NSTG;
        LDFRAG1(0, stb, 0);
        #pragma unroll
        for (int kk = 0; kk < TKC; kk += 16) {
            int cur = (kk >> 4) & 1;
            if (pre) ISSUE1_PART(c + 2, s2, kk >> 4);
            if (kk + 16 < TKC) LDFRAG1(cur ^ 1, stb, kk + 16);
            #pragma unroll
            for (int h = 0; h < 2; h++)
                #pragma unroll
                for (int mt = 0; mt < 4; mt++)
                    #pragma unroll
                    for (int nt = 0; nt < 4; nt++)
                        mma16(acc[h][mt][nt], af[cur][mt], bf[cur][h][nt]);
        }
        if (pre) CP_COMMIT();
    }

    const float* b1e  = b1 + (size_t)e * 2 * FF;
    __half*      acte = g_acth + (size_t)e * MAXT * FF;
    #pragma unroll
    for (int mt = 0; mt < 4; mt++)
        #pragma unroll
        for (int rr = 0; rr < 2; rr++) {
            int mg = m0 + wm + mt * 16 + g + rr * 8;
            if (mg >= cnt) continue;
            __half* orow = acte + (size_t)mg * FF;
            #pragma unroll
            for (int nt = 0; nt < 4; nt++) {
                int col = n0 + wn + nt * 8 + tig * 2;
                float h1a = acc[0][mt][nt][rr * 2 + 0] + b1e[col];
                float h1b = acc[0][mt][nt][rr * 2 + 1] + b1e[col + 1];
                float h2a = acc[1][mt][nt][rr * 2 + 0] + b1e[FF + col];
                float h2b = acc[1][mt][nt][rr * 2 + 1] + b1e[FF + col + 1];
                float oa = h1a * h2a / (1.f + __expf(-h2a));
                float ob = h1b * h2b / (1.f + __expf(-h2b));
                *(__half2*)(orow + col) = __floats2half2_rn(oa, ob);
            }
        }
    #undef ISSUE1
    #undef ISSUE1_PART
    #undef LDFRAG1
}

// ---------------------------------------------------------------------------
// GEMM2: CTA 128(M) x 128(N); 4 warps 2x2; warp tile 64x64; atomic scatter.
__global__ __launch_bounds__(128, 2) void gemm2_k(const float* __restrict__ b2,
                                                  float* __restrict__ out) {
    int e   = blockIdx.z;
    int cnt = g_cnt[e];
    int m0  = blockIdx.y * 128;
    if (m0 >= cnt) return;
    int n0  = blockIdx.x * 128;

    extern __shared__ uint32_t dynw[];
    uint32_t sb = smem_u32(dynw);
    __shared__ int   toks[128];
    __shared__ float wts[128];

    int tid = threadIdx.x, wid = tid >> 5, lane = tid & 31;
    int g = lane >> 2, tig = lane & 3;
    int wm = (wid & 1) * 64, wn = (wid >> 1) * 64;

    int sel = lane >> 3, r7 = lane & 7;
    int      arow_off = r7 + ((sel & 1) << 3);
    uint32_t axoff    = (uint32_t)((((sel >> 1) ^ r7) << 4));
    int      brow_off = r7 + ((sel >> 1) << 3);
    uint32_t bxoff    = (uint32_t)((((sel & 1) ^ r7) << 4));

    if (tid < 128) {
        int m = m0 + tid;
        toks[tid] = (m < cnt) ? g_tok[e * MAXT + m] : -1;
        wts[tid]  = (m < cnt) ? g_wt[e * MAXT + m] : 0.f;
    }
    __syncthreads();

    const __half* W2e  = g_w2h + (size_t)e * DM * FF;
    const __half* acte = g_acth + (size_t)e * MAXT * FF;

    float acc[4][8][4];
    #pragma unroll
    for (int mt = 0; mt < 4; mt++)
        #pragma unroll
        for (int nt = 0; nt < 8; nt++)
            #pragma unroll
            for (int j = 0; j < 4; j++) acc[mt][nt][j] = 0.f;

    const int NC = FF / TKC;    // 32

    #define ISSUE2_PART(c, s, p) do {                                           \
        int k0_ = (c) * TKC;                                                    \
        uint32_t st_ = sb + (uint32_t)(s) * STGB;                               \
        _Pragma("unroll")                                                       \
        for (int i_ = (p) * 4; i_ < (p) * 4 + 4; i_++) {                        \
            int idx_ = tid + i_ * 128, row_ = idx_ >> 3, q_ = idx_ & 7;         \
            uint32_t dst_ = st_ + swo(row_, q_) * 4;                            \
            if (row_ < 128) {                                                   \
                int ok_ = (m0 + row_ < cnt);                                    \
                const __half* src_ = acte + (size_t)(m0 + (ok_ ? row_ : 0)) * FF\
                                     + k0_ + q_ * 8;                            \
                cpa16(dst_, src_, ok_ ? 16 : 0);                                \
            } else {                                                            \
                int j_ = row_ - 128;                                            \
                const __half* src_ = W2e + (size_t)(n0 + j_) * FF + k0_ + q_ * 8;\
                cpa16(dst_, src_, 16);                                          \
            }                                                                   \
        }                                                                       \
    } while (0)

    #define ISSUE2(c, s) do {                                                   \
        ISSUE2_PART(c, s, 0); ISSUE2_PART(c, s, 1);                             \
        ISSUE2_PART(c, s, 2); ISSUE2_PART(c, s, 3);                             \
        CP_COMMIT();                                                            \
    } while (0)

    #define LDFRAG2(buf, stb, kk) do {                                          \
        uint32_t qx_ = ((uint32_t)((kk) >> 3)) << 4;                            \
        _Pragma("unroll")                                                       \
        for (int mt = 0; mt < 4; mt++)                                          \
            ldsm4(af[buf][mt],                                                  \
                  (stb) + (uint32_t)((wm + mt * 16 + arow_off) * 128)           \
                        + (axoff ^ qx_));                                       \
        _Pragma("unroll")                                                       \
        for (int np = 0; np < 4; np++)                                          \
            ldsm4(&bf[buf][np * 2][0],                                          \
                  (stb) + (uint32_t)((128 + wn + np * 16 + brow_off) * 128)     \
                        + (bxoff ^ qx_));                                       \
    } while (0)

    ISSUE2(0, 0); ISSUE2(1, 1);

    uint32_t af[2][4][4];
    uint32_t bf[2][8][2];

    for (int c = 0; c < NC; ++c) {
        if (c + 1 < NC) CP_WAIT1(); else CP_WAIT0();
        __syncthreads();
        uint32_t stb = sb + (uint32_t)(c % NSTG) * STGB;
        int pre = (c + 2 < NC);
        int s2  = (c + 2) % NSTG;
        LDFRAG2(0, stb, 0);
        #pragma unroll
        for (int kk = 0; kk < TKC; kk += 16) {
            int cur = (kk >> 4) & 1;
            if (pre) ISSUE2_PART(c + 2, s2, kk >> 4);
            if (kk + 16 < TKC) LDFRAG2(cur ^ 1, stb, kk + 16);
            #pragma unroll
            for (int mt = 0; mt < 4; mt++)
                #pragma unroll
                for (int nt = 0; nt < 8; nt++)
                    mma16(acc[mt][nt], af[cur][mt], bf[cur][nt]);
        }
        if (pre) CP_COMMIT();
    }

    const float* b2e = b2 + (size_t)e * DM;
    #pragma unroll
    for (int mt = 0; mt < 4; mt++)
        #pragma unroll
        for (int rr = 0; rr < 2; rr++) {
            int lm = wm + mt * 16 + g + rr * 8;
            int mg = m0 + lm;
            if (mg >= cnt) continue;
            int   tok = toks[lm];
            float w   = wts[lm];
            float* dst = out + (size_t)tok * DM;
            #pragma unroll
            for (int nt = 0; nt < 8; nt++) {
                int col = n0 + wn + nt * 8 + tig * 2;
                atomicAdd(dst + col,     w * (acc[mt][nt][rr * 2 + 0] + b2e[col]));
                atomicAdd(dst + col + 1, w * (acc[mt][nt][rr * 2 + 1] + b2e[col + 1]));
            }
        }
    #undef ISSUE2
    #undef ISSUE2_PART
    #undef LDFRAG2
}

// ---------------------------------------------------------------------------
extern "C" void kernel_launch(void* const* d_in, const int* in_sizes, int n_in,
                              void* d_out, int out_size) {
    const float* x    = (const float*)d_in[0];
    const float* Wr   = (const float*)d_in[1];
    const float* temp = (const float*)d_in[2];
    const float* W1   = (const float*)d_in[3];
    const float* b1   = (const float*)d_in[4];
    const float* W2   = (const float*)d_in[5];
    const float* b2   = (const float*)d_in[6];
    float* out = (float*)d_out;

    int T  = in_sizes[0] / DM;
    int MB = (T + 127) / 128;

    static __half *p_w1h = nullptr, *p_w2h = nullptr;
    static cudaStream_t s1, s2;
    static cudaEvent_t ev0a, ev0b, ev1, ev2;
    static bool inited = false;
    if (!inited) {
        cudaGetSymbolAddress((void**)&p_w1h, g_w1h);
        cudaGetSymbolAddress((void**)&p_w2h, g_w2h);
        cudaStreamCreateWithFlags(&s1, cudaStreamNonBlocking);
        cudaStreamCreateWithFlags(&s2, cudaStreamNonBlocking);
        cudaEventCreateWithFlags(&ev0a, cudaEventDisableTiming);
        cudaEventCreateWithFlags(&ev0b, cudaEventDisableTiming);
        cudaEventCreateWithFlags(&ev1, cudaEventDisableTiming);
        cudaEventCreateWithFlags(&ev2, cudaEventDisableTiming);
        const int DSM = NSTG * STGB;   // 98304
        cudaFuncSetAttribute(gemm1_k, cudaFuncAttributeMaxDynamicSharedMemorySize, DSM);
        cudaFuncSetAttribute(gemm2_k, cudaFuncAttributeMaxDynamicSharedMemorySize, DSM);
        inited = true;
    }
    const int DSM = NSTG * STGB;

    // fork: weight conversions run parallel with router/memset
    cudaEventRecord(ev0a, 0);
    cudaStreamWaitEvent(s1, ev0a, 0);
    cudaEventRecord(ev0b, 0);
    cudaStreamWaitEvent(s2, ev0b, 0);

    cvt16_k<<<592, 256, 0, s1>>>(W1, p_w1h, NE * 2 * FF * DM / 4);
    cvt16_k<<<592, 256, 0, s2>>>(W2, p_w2h, NE * DM * FF / 4);

    cudaMemsetAsync(d_out, 0, (size_t)out_size * sizeof(float), 0);
    init_k<<<1, 32, 0, 0>>>();
    router_k<<<T, 256, 0, 0>>>(x, Wr, temp);

    // join W1 before gemm1
    cudaEventRecord(ev1, s1);
    cudaStreamWaitEvent(0, ev1, 0);

    dim3 g1(FF / 64, MB, NE);
    gemm1_k<<<g1, 128, DSM, 0>>>(b1);

    // join W2 before gemm2
    cudaEventRecord(ev2, s2);
    cudaStreamWaitEvent(0, ev2, 0);

    dim3 g2(DM / 128, MB, NE);
    gemm2_k<<<g2, 128, DSM, 0>>>(b2, out);
}